// round 6
// baseline (speedup 1.0000x reference)
#include <cuda_runtime.h>
#include <cuda_fp16.h>
#include <stdint.h>

#define NROWS  16384
#define NCODES 8192
#define KDIM   256
#define ZELEMS (NROWS * KDIM)
#define B1 16.0f
#define B2 40.0f

typedef __half fp16;

__device__ float g_Y[(size_t)NROWS * NCODES];          // logits+gumbel
__device__ fp16  g_Whi[(size_t)NROWS * NCODES];
__device__ fp16  g_Wlo[(size_t)NROWS * NCODES];
__device__ fp16  g_Ahi[ZELEMS], g_Alo[ZELEMS];
__device__ fp16  g_Bhi[NCODES * KDIM], g_Blo[NCODES * KDIM];
__device__ fp16  g_CThi[(size_t)KDIM * NCODES], g_CTlo[(size_t)KDIM * NCODES];
// per-(ntile,row) partials from gemm1 epilogue
__device__ float g_pmx[64 * NROWS];
__device__ int   g_pai[64 * NROWS];
__device__ float g_pse[64 * NROWS];
__device__ float g_psel[64 * NROWS];
__device__ float g_psy[64 * NROWS];
__device__ float g_kl[NROWS];
__device__ float g_winv[NROWS];
__device__ float g_sse[256];

// ---------------- PTX helpers ----------------------------------------------
__device__ __forceinline__ uint32_t smem_u32(const void* p) {
    uint32_t a;
    asm("{ .reg .u64 t; cvta.to.shared.u64 t, %1; cvt.u32.u64 %0, t; }" : "=r"(a) : "l"(p));
    return a;
}
__device__ __forceinline__ void cp16(uint32_t dst, const void* src) {
    asm volatile("cp.async.cg.shared.global [%0], [%1], 16;\n" :: "r"(dst), "l"(src));
}
__device__ __forceinline__ void cp_commit() { asm volatile("cp.async.commit_group;\n" ::: "memory"); }
template<int N> __device__ __forceinline__ void cp_wait() {
    asm volatile("cp.async.wait_group %0;\n" :: "n"(N) : "memory");
}
__device__ __forceinline__ void ldsm4(uint32_t* r, uint32_t addr) {
    asm volatile("ldmatrix.sync.aligned.m8n8.x4.shared.b16 {%0,%1,%2,%3}, [%4];"
        : "=r"(r[0]), "=r"(r[1]), "=r"(r[2]), "=r"(r[3]) : "r"(addr));
}
__device__ __forceinline__ void mma16816(float* c, const uint32_t* a, const uint32_t* b) {
    asm volatile("mma.sync.aligned.m16n8k16.row.col.f32.f16.f16.f32 "
        "{%0,%1,%2,%3}, {%4,%5,%6,%7}, {%8,%9}, {%0,%1,%2,%3};"
        : "+f"(c[0]), "+f"(c[1]), "+f"(c[2]), "+f"(c[3])
        : "r"(a[0]), "r"(a[1]), "r"(a[2]), "r"(a[3]), "r"(b[0]), "r"(b[1]));
}

// ---------------- threefry2x32 key (0,42) + gumbel --------------------------
__device__ __forceinline__ uint2 tf2x32(uint32_t x0, uint32_t x1) {
    const uint32_t ks1 = 42u, ks2 = 0x1BD11BDAu ^ 42u;
    x1 += ks1;
#define TFR(r) { x0 += x1; x1 = (x1 << (r)) | (x1 >> (32 - (r))); x1 ^= x0; }
    TFR(13) TFR(15) TFR(26) TFR(6)
    x0 += ks1; x1 += ks2 + 1u;
    TFR(17) TFR(29) TFR(16) TFR(24)
    x0 += ks2; x1 += 2u;
    TFR(13) TFR(15) TFR(26) TFR(6)
    x1 += ks1 + 3u;
    TFR(17) TFR(29) TFR(16) TFR(24)
    x0 += ks1; x1 += ks2 + 4u;
    TFR(13) TFR(15) TFR(26) TFR(6)
    x0 += ks2; x1 += 5u;
#undef TFR
    return make_uint2(x0, x1);
}
__device__ __forceinline__ float gumbel_at(uint32_t j) {
    uint2 t = tf2x32(0u, j);
    uint32_t bits = t.x ^ t.y;
    float f = __uint_as_float((bits >> 9) | 0x3f800000u) - 1.0f;
    f = fmaxf(f, 1.17549435e-38f);
    float tt = f - 1.0f;
    float inner;
    if (tt > -0.00390625f)
        inner = tt * (1.0f + tt * (-0.5f + tt * 0.33333333f));
    else
        inner = __logf(f);
    return -__logf(-inner);
}

// ---------------- block reductions ------------------------------------------
__device__ __forceinline__ float blockSum(float v, float* sc) {
    int lane = threadIdx.x & 31, w = threadIdx.x >> 5;
#pragma unroll
    for (int o = 16; o; o >>= 1) v += __shfl_xor_sync(0xffffffffu, v, o);
    if (lane == 0) sc[w] = v;
    __syncthreads();
    if (w == 0) {
        float x = (lane < 8) ? sc[lane] : 0.f;
#pragma unroll
        for (int o = 4; o; o >>= 1) x += __shfl_xor_sync(0xffffffffu, x, o);
        if (lane == 0) sc[0] = x;
    }
    __syncthreads();
    float r = sc[0];
    __syncthreads();
    return r;
}

// ---------------- split kernels ---------------------------------------------
__global__ __launch_bounds__(256) void split_z(const float* __restrict__ z) {
    int i = blockIdx.x * 256 + threadIdx.x;
    float x = z[i];
    fp16 h = __float2half_rn(x);
    g_Ahi[i] = h;
    g_Alo[i] = __float2half_rn(x - __half2float(h));
}
__global__ __launch_bounds__(256) void split_cb(const float* __restrict__ cb) {
    __shared__ fp16 th[64][65], tl[64][65];
    int bc = blockIdx.x * 64, bd = blockIdx.y * 64;
    int t = threadIdx.x;
#pragma unroll 4
    for (int cc = 0; cc < 16; cc++) {
        int c = (t >> 6) * 16 + cc;
        int d = t & 63;
        size_t gi = (size_t)(bc + c) * KDIM + bd + d;
        float x = cb[gi];
        fp16 h = __float2half_rn(x);
        fp16 l = __float2half_rn(x - __half2float(h));
        g_Bhi[gi] = h; g_Blo[gi] = l;
        th[c][d] = h; tl[c][d] = l;
    }
    __syncthreads();
#pragma unroll 4
    for (int dd = 0; dd < 16; dd++) {
        int d = (t >> 6) * 16 + dd;
        int c = t & 63;
        size_t gi = (size_t)(bd + d) * NCODES + bc + c;
        g_CThi[gi] = th[c][d];
        g_CTlo[gi] = tl[c][d];
    }
}

// ---------------- fused single-pass 3-term HMMA GEMM ------------------------
// Tile 128x128, 4 warps of 64x64, BK=32; smem stage holds Ahi/Alo/Bhi/Blo.
// MODE 0: logits GEMM + fused gumbel/stat epilogue (writes y + partials)
// MODE 1: z_q GEMM + z_q_st/SSE epilogue
#define ARR_B  10240u          // 128 rows * 80 bytes
#define STAGE_B 40960u
#define DSMEM  (2 * STAGE_B)

template<int MODE>
__global__ __launch_bounds__(128) void gemm_mma(const float* __restrict__ Z,
                                                float* __restrict__ Out) {
    extern __shared__ char dyn[];
    __shared__ float sred_mx[128], sred_se[128], sred_sel[128], sred_sy[128];
    __shared__ int   sred_ai[128];
    __shared__ float ssum[4];

    uint32_t sm = smem_u32(dyn);
    int tid = threadIdx.x, lane = tid & 31, wid = tid >> 5;
    int wm = wid >> 1, wn = wid & 1;
    int n0 = blockIdx.x * 128, m0 = blockIdx.y * 128;

    const int NIT = (MODE == 0) ? 8 : 256;
    const int sAs = (MODE == 0) ? KDIM : NCODES;
    const fp16* Ah = (MODE == 0) ? g_Ahi : g_Whi;
    const fp16* Al = (MODE == 0) ? g_Alo : g_Wlo;
    const fp16* Bh = (MODE == 0) ? g_Bhi : g_CThi;
    const fp16* Bl = (MODE == 0) ? g_Blo : g_CTlo;

    float acc[4][8][4] = {};

    auto load_stage = [&](int it, int s) {
        int k0 = it * 32;
        uint32_t base = sm + s * STAGE_B;
#pragma unroll
        for (int i = 0; i < 16; i++) {
            int idx = tid + i * 128;              // 0..2047
            int arr = idx >> 9;                   // 0..3
            int row = (idx >> 2) & 127;
            int ch  = idx & 3;
            const fp16* src;
            if (arr == 0)      src = Ah + (size_t)(m0 + row) * sAs + k0 + ch * 8;
            else if (arr == 1) src = Al + (size_t)(m0 + row) * sAs + k0 + ch * 8;
            else if (arr == 2) src = Bh + (size_t)(n0 + row) * sAs + k0 + ch * 8;
            else               src = Bl + (size_t)(n0 + row) * sAs + k0 + ch * 8;
            cp16(base + arr * ARR_B + row * 80 + ch * 16, src);
        }
        cp_commit();
    };

    load_stage(0, 0);
    for (int it = 0; it < NIT; it++) {
        int s = it & 1;
        cp_wait<0>();
        __syncthreads();
        if (it + 1 < NIT) load_stage(it + 1, s ^ 1);

        uint32_t da_h = sm + s * STAGE_B;
        uint32_t da_l = da_h + ARR_B;
        uint32_t db_h = da_h + 2 * ARR_B;
        uint32_t db_l = da_h + 3 * ARR_B;
#pragma unroll
        for (int ks = 0; ks < 32; ks += 16) {
            uint32_t ah[4][4], al[4][4], bq[4][4];
            uint32_t aoff = (uint32_t)((wm * 64 + (lane & 15)) * 80 + (ks + ((lane >> 4) << 3)) * 2);
            uint32_t boff = (uint32_t)((wn * 64 + (lane & 7) + ((lane >> 4) << 3)) * 80
                                       + (ks + (((lane >> 3) & 1) << 3)) * 2);
#pragma unroll
            for (int mt = 0; mt < 4; mt++) {
                ldsm4(ah[mt], da_h + aoff + mt * 16 * 80);
                ldsm4(al[mt], da_l + aoff + mt * 16 * 80);
            }
#pragma unroll
            for (int np = 0; np < 4; np++)
                ldsm4(bq[np], db_h + boff + np * 16 * 80);
#pragma unroll
            for (int mt = 0; mt < 4; mt++)
#pragma unroll
                for (int nt = 0; nt < 8; nt++) {
                    mma16816(acc[mt][nt], ah[mt], &bq[nt >> 1][(nt & 1) * 2]);
                    mma16816(acc[mt][nt], al[mt], &bq[nt >> 1][(nt & 1) * 2]);
                }
#pragma unroll
            for (int np = 0; np < 4; np++)
                ldsm4(bq[np], db_l + boff + np * 16 * 80);
#pragma unroll
            for (int mt = 0; mt < 4; mt++)
#pragma unroll
                for (int nt = 0; nt < 8; nt++)
                    mma16816(acc[mt][nt], ah[mt], &bq[nt >> 1][(nt & 1) * 2]);
        }
    }

    // ---------------- epilogue ----------------
    if (MODE == 0) {
        // fused gumbel + per-row stats; writes y only
        float mx[8], se[8], sel[8], sy[8];
        int ai[8];
#pragma unroll
        for (int s = 0; s < 8; s++) { mx[s] = -3.4e38f; ai[s] = 0; se[s] = 0.f; sel[s] = 0.f; sy[s] = 0.f; }
#pragma unroll
        for (int mt = 0; mt < 4; mt++)
#pragma unroll
            for (int nt = 0; nt < 8; nt++) {
                int c = n0 + wn * 64 + nt * 8 + (lane & 3) * 2;
#pragma unroll
                for (int h = 0; h < 2; h++) {
                    int r = m0 + wm * 64 + (lane >> 2) + mt * 16 + h * 8;
                    int s = mt * 2 + h;
                    uint32_t jb = (uint32_t)r * (uint32_t)NCODES + (uint32_t)c;
                    float l0 = acc[mt][nt][h * 2], l1 = acc[mt][nt][h * 2 + 1];
                    float y0 = l0 + gumbel_at(jb);
                    float y1 = l1 + gumbel_at(jb + 1u);
                    *(float2*)(g_Y + (size_t)r * NCODES + c) = make_float2(y0, y1);
                    float e0 = __expf(l0 - B1), e1 = __expf(l1 - B1);
                    se[s] += e0 + e1;
                    sel[s] += e0 * l0 + e1 * l1;
                    sy[s] += __expf(y0 - B2) + __expf(y1 - B2);
                    if (l0 > mx[s]) { mx[s] = l0; ai[s] = c; }
                    if (l1 > mx[s]) { mx[s] = l1; ai[s] = c + 1; }
                }
            }
        // reduce over 4 lanes sharing each row
#pragma unroll
        for (int s = 0; s < 8; s++) {
#pragma unroll
            for (int o = 1; o <= 2; o <<= 1) {
                float omx = __shfl_xor_sync(0xffffffffu, mx[s], o);
                int   oai = __shfl_xor_sync(0xffffffffu, ai[s], o);
                se[s]  += __shfl_xor_sync(0xffffffffu, se[s], o);
                sel[s] += __shfl_xor_sync(0xffffffffu, sel[s], o);
                sy[s]  += __shfl_xor_sync(0xffffffffu, sy[s], o);
                if (omx > mx[s] || (omx == mx[s] && oai < ai[s])) { mx[s] = omx; ai[s] = oai; }
            }
        }
        if (wn == 0 && (lane & 3) == 0) {
#pragma unroll
            for (int s = 0; s < 8; s++) {
                int rl = wm * 64 + (lane >> 2) + (s >> 1) * 16 + (s & 1) * 8;
                sred_mx[rl] = mx[s]; sred_ai[rl] = ai[s];
                sred_se[rl] = se[s]; sred_sel[rl] = sel[s]; sred_sy[rl] = sy[s];
            }
        }
        __syncthreads();
        if (wn == 1 && (lane & 3) == 0) {
#pragma unroll
            for (int s = 0; s < 8; s++) {
                int rl = wm * 64 + (lane >> 2) + (s >> 1) * 16 + (s & 1) * 8;
                float omx = sred_mx[rl]; int oai = sred_ai[rl];
                if (omx > mx[s] || (omx == mx[s] && oai < ai[s])) { mx[s] = omx; ai[s] = oai; }
                size_t p = (size_t)blockIdx.x * NROWS + (m0 + rl);
                g_pmx[p] = mx[s]; g_pai[p] = ai[s];
                g_pse[p] = se[s] + sred_se[rl];
                g_psel[p] = sel[s] + sred_sel[rl];
                g_psy[p] = sy[s] + sred_sy[rl];
            }
        }
    } else {
        int rbase = m0 + wm * 64 + (lane >> 2);
        int cbase = n0 + wn * 64 + (lane & 3) * 2;
        float sse = 0.f;
#pragma unroll
        for (int mt = 0; mt < 4; mt++)
#pragma unroll
            for (int nt = 0; nt < 8; nt++) {
                int r0 = rbase + mt * 16, c0 = cbase + nt * 8;
#pragma unroll
                for (int h = 0; h < 2; h++) {
                    size_t o = (size_t)(r0 + h * 8) * KDIM + c0;
                    float2 zv = *(const float2*)(Z + o);
                    float dx = acc[mt][nt][h * 2]     - zv.x;
                    float dy = acc[mt][nt][h * 2 + 1] - zv.y;
                    sse += dx * dx + dy * dy;
                    *(float2*)(Out + o) = make_float2(zv.x + dx, zv.y + dy);
                }
            }
#pragma unroll
        for (int o = 16; o; o >>= 1) sse += __shfl_xor_sync(0xffffffffu, sse, o);
        if (lane == 0) ssum[wid] = sse;
        __syncthreads();
        if (tid == 0)
            g_sse[blockIdx.y * 2 + blockIdx.x] = ssum[0] + ssum[1] + ssum[2] + ssum[3];
    }
}

// ---------------- rowred: 64 partials per row -> code, KL, 1/SY -------------
__global__ __launch_bounds__(256) void rowred(float* __restrict__ outCodes) {
    int w = threadIdx.x >> 5, lane = threadIdx.x & 31;
    int r = blockIdx.x * 8 + w;
    float mx = -3.4e38f, se = 0.f, sel = 0.f, sy = 0.f;
    int ai = 0x7fffffff;
#pragma unroll
    for (int half = 0; half < 2; half++) {
        int nt = lane + half * 32;
        size_t p = (size_t)nt * NROWS + r;
        float omx = g_pmx[p]; int oai = g_pai[p];
        if (omx > mx || (omx == mx && oai < ai)) { mx = omx; ai = oai; }
        se += g_pse[p]; sel += g_psel[p]; sy += g_psy[p];
    }
#pragma unroll
    for (int o = 16; o; o >>= 1) {
        float omx = __shfl_xor_sync(0xffffffffu, mx, o);
        int   oai = __shfl_xor_sync(0xffffffffu, ai, o);
        se  += __shfl_xor_sync(0xffffffffu, se, o);
        sel += __shfl_xor_sync(0xffffffffu, sel, o);
        sy  += __shfl_xor_sync(0xffffffffu, sy, o);
        if (omx > mx || (omx == mx && oai < ai)) { mx = omx; ai = oai; }
    }
    if (lane == 0) {
        outCodes[r] = (float)ai;
        g_kl[r] = sel / se - (B1 + __logf(se)) + 9.0109131f;   // + ln 8192
        g_winv[r] = 1.0f / sy;
    }
}

// ---------------- wpass: y -> W hi/lo ---------------------------------------
__global__ __launch_bounds__(256) void wpass() {
    int idx = blockIdx.x * 256 + threadIdx.x;          // float4 index
    float4 y = *(const float4*)(g_Y + (size_t)idx * 4);
    float inv = g_winv[idx >> 11];                     // 2048 float4s per row
    float w0 = __expf(y.x - B2) * inv;
    float w1 = __expf(y.y - B2) * inv;
    float w2 = __expf(y.z - B2) * inv;
    float w3 = __expf(y.w - B2) * inv;
    fp16 h0 = __float2half_rn(w0), h1 = __float2half_rn(w1);
    fp16 h2 = __float2half_rn(w2), h3 = __float2half_rn(w3);
    __half2 hh0 = __halves2half2(h0, h1), hh1 = __halves2half2(h2, h3);
    __half2 ll0 = __halves2half2(__float2half_rn(w0 - __half2float(h0)),
                                 __float2half_rn(w1 - __half2float(h1)));
    __half2 ll1 = __halves2half2(__float2half_rn(w2 - __half2float(h2)),
                                 __float2half_rn(w3 - __half2float(h3)));
    *(__half2*)(g_Whi + (size_t)idx * 4)     = hh0;
    *(__half2*)(g_Whi + (size_t)idx * 4 + 2) = hh1;
    *(__half2*)(g_Wlo + (size_t)idx * 4)     = ll0;
    *(__half2*)(g_Wlo + (size_t)idx * 4 + 2) = ll1;
}

// ---------------- finalize --------------------------------------------------
__global__ __launch_bounds__(256) void finalize(float* __restrict__ outLoss) {
    __shared__ float sc[8];
    float k = 0.f;
    for (int i = threadIdx.x; i < NROWS; i += 256) k += g_kl[i];
    float K = blockSum(k, sc);
    float E = blockSum(g_sse[threadIdx.x], sc);
    if (threadIdx.x == 0)
        outLoss[0] = 0.25f * (E / (float)ZELEMS) + 0.01f * (K / (float)NROWS);
}

// ---------------- launch ----------------------------------------------------
extern "C" void kernel_launch(void* const* d_in, const int* in_sizes, int n_in,
                              void* d_out, int out_size) {
    const float* z  = (const float*)d_in[0];
    const float* cb = (const float*)d_in[1];
    float* out = (float*)d_out;
    float* outZ     = out;
    float* outLoss  = out + ZELEMS;
    float* outCodes = out + ZELEMS + 1;

    cudaFuncSetAttribute(gemm_mma<0>, cudaFuncAttributeMaxDynamicSharedMemorySize, DSMEM);
    cudaFuncSetAttribute(gemm_mma<1>, cudaFuncAttributeMaxDynamicSharedMemorySize, DSMEM);

    split_z<<<ZELEMS / 256, 256>>>(z);
    dim3 gs(NCODES / 64, KDIM / 64);
    split_cb<<<gs, 256>>>(cb);

    dim3 g1(NCODES / 128, NROWS / 128);          // (64, 128)
    gemm_mma<0><<<g1, 128, DSMEM>>>(nullptr, nullptr);

    rowred<<<NROWS / 8, 256>>>(outCodes);
    wpass<<<ZELEMS * 8 / 256, 256>>>();          // 134M elems / 4 per thread

    dim3 g2(KDIM / 128, NROWS / 128);            // (2, 128)
    gemm_mma<1><<<g2, 128, DSMEM>>>(z, outZ);

    finalize<<<1, 256>>>(outLoss);
}

// round 7
// speedup vs baseline: 1.1880x; 1.1880x over previous
#include <cuda_runtime.h>
#include <cuda_fp16.h>
#include <stdint.h>

#define NROWS  16384
#define NCODES 8192
#define KDIM   256
#define ZELEMS (NROWS * KDIM)
#define B1 16.0f
#define B2 40.0f

typedef __half fp16;

__device__ float g_logits[(size_t)NROWS * NCODES];
__device__ float g_G[(size_t)NROWS * NCODES];          // gumbel noise
__device__ fp16  g_Whi[(size_t)NROWS * NCODES];
__device__ fp16  g_Wlo[(size_t)NROWS * NCODES];
__device__ fp16  g_Ahi[ZELEMS], g_Alo[ZELEMS];
__device__ fp16  g_Bhi[NCODES * KDIM], g_Blo[NCODES * KDIM];
__device__ fp16  g_CThi[(size_t)KDIM * NCODES], g_CTlo[(size_t)KDIM * NCODES];
__device__ float g_kl[NROWS];
__device__ float g_sse[256];

// ---------------- PTX helpers ----------------------------------------------
__device__ __forceinline__ uint32_t smem_u32(const void* p) {
    uint32_t a;
    asm("{ .reg .u64 t; cvta.to.shared.u64 t, %1; cvt.u32.u64 %0, t; }" : "=r"(a) : "l"(p));
    return a;
}
__device__ __forceinline__ void cp16(uint32_t dst, const void* src) {
    asm volatile("cp.async.cg.shared.global [%0], [%1], 16;\n" :: "r"(dst), "l"(src));
}
__device__ __forceinline__ void cp_commit() { asm volatile("cp.async.commit_group;\n" ::: "memory"); }
template<int N> __device__ __forceinline__ void cp_wait() {
    asm volatile("cp.async.wait_group %0;\n" :: "n"(N) : "memory");
}
__device__ __forceinline__ void ldsm4(uint32_t* r, uint32_t addr) {
    asm volatile("ldmatrix.sync.aligned.m8n8.x4.shared.b16 {%0,%1,%2,%3}, [%4];"
        : "=r"(r[0]), "=r"(r[1]), "=r"(r[2]), "=r"(r[3]) : "r"(addr));
}
__device__ __forceinline__ void mma16816(float* c, const uint32_t* a, const uint32_t* b) {
    asm volatile("mma.sync.aligned.m16n8k16.row.col.f32.f16.f16.f32 "
        "{%0,%1,%2,%3}, {%4,%5,%6,%7}, {%8,%9}, {%0,%1,%2,%3};"
        : "+f"(c[0]), "+f"(c[1]), "+f"(c[2]), "+f"(c[3])
        : "r"(a[0]), "r"(a[1]), "r"(a[2]), "r"(a[3]), "r"(b[0]), "r"(b[1]));
}

// ---------------- threefry2x32 key (0,42) + gumbel --------------------------
__device__ __forceinline__ uint2 tf2x32(uint32_t x0, uint32_t x1) {
    const uint32_t ks1 = 42u, ks2 = 0x1BD11BDAu ^ 42u;
    x1 += ks1;
#define TFR(r) { x0 += x1; x1 = (x1 << (r)) | (x1 >> (32 - (r))); x1 ^= x0; }
    TFR(13) TFR(15) TFR(26) TFR(6)
    x0 += ks1; x1 += ks2 + 1u;
    TFR(17) TFR(29) TFR(16) TFR(24)
    x0 += ks2; x1 += 2u;
    TFR(13) TFR(15) TFR(26) TFR(6)
    x1 += ks1 + 3u;
    TFR(17) TFR(29) TFR(16) TFR(24)
    x0 += ks1; x1 += ks2 + 4u;
    TFR(13) TFR(15) TFR(26) TFR(6)
    x0 += ks2; x1 += 5u;
#undef TFR
    return make_uint2(x0, x1);
}
__device__ __forceinline__ float gumbel_at(uint32_t j) {
    uint2 t = tf2x32(0u, j);
    uint32_t bits = t.x ^ t.y;
    float f = __uint_as_float((bits >> 9) | 0x3f800000u) - 1.0f;
    f = fmaxf(f, 1.17549435e-38f);
    float tt = f - 1.0f;
    float inner;
    if (tt > -0.00390625f)
        inner = tt * (1.0f + tt * (-0.5f + tt * 0.33333333f));
    else
        inner = __logf(f);
    return -__logf(-inner);
}

// ---------------- reductions (256 threads) ----------------------------------
__device__ __forceinline__ float blockSum(float v, float* sc) {
    int lane = threadIdx.x & 31, w = threadIdx.x >> 5;
#pragma unroll
    for (int o = 16; o; o >>= 1) v += __shfl_xor_sync(0xffffffffu, v, o);
    if (lane == 0) sc[w] = v;
    __syncthreads();
    if (w == 0) {
        float x = (lane < 8) ? sc[lane] : 0.f;
#pragma unroll
        for (int o = 4; o; o >>= 1) x += __shfl_xor_sync(0xffffffffu, x, o);
        if (lane == 0) sc[0] = x;
    }
    __syncthreads();
    float r = sc[0];
    __syncthreads();
    return r;
}
__device__ __forceinline__ void blockArgmax(float& v, int& idx, float* scv, int* sci) {
    int lane = threadIdx.x & 31, w = threadIdx.x >> 5;
#pragma unroll
    for (int o = 16; o; o >>= 1) {
        float ov = __shfl_xor_sync(0xffffffffu, v, o);
        int   oi = __shfl_xor_sync(0xffffffffu, idx, o);
        if (ov > v || (ov == v && oi < idx)) { v = ov; idx = oi; }
    }
    if (lane == 0) { scv[w] = v; sci[w] = idx; }
    __syncthreads();
    if (w == 0) {
        float x = (lane < 8) ? scv[lane] : -3.4e38f;
        int   i = (lane < 8) ? sci[lane] : 0x7fffffff;
#pragma unroll
        for (int o = 4; o; o >>= 1) {
            float ov = __shfl_xor_sync(0xffffffffu, x, o);
            int   oi = __shfl_xor_sync(0xffffffffu, i, o);
            if (ov > x || (ov == x && oi < i)) { x = ov; i = oi; }
        }
        if (lane == 0) { scv[0] = x; sci[0] = i; }
    }
    __syncthreads();
    v = scv[0]; idx = sci[0];
    __syncthreads();
}

// ---------------- split kernels ---------------------------------------------
__global__ __launch_bounds__(256) void split_z(const float* __restrict__ z) {
    int i = blockIdx.x * 256 + threadIdx.x;
    float x = z[i];
    fp16 h = __float2half_rn(x);
    g_Ahi[i] = h;
    g_Alo[i] = __float2half_rn(x - __half2float(h));
}
__global__ __launch_bounds__(256) void split_cb(const float* __restrict__ cb) {
    __shared__ fp16 th[64][65], tl[64][65];
    int bc = blockIdx.x * 64, bd = blockIdx.y * 64;
    int t = threadIdx.x;
#pragma unroll 4
    for (int cc = 0; cc < 16; cc++) {
        int c = (t >> 6) * 16 + cc;
        int d = t & 63;
        size_t gi = (size_t)(bc + c) * KDIM + bd + d;
        float x = cb[gi];
        fp16 h = __float2half_rn(x);
        fp16 l = __float2half_rn(x - __half2float(h));
        g_Bhi[gi] = h; g_Blo[gi] = l;
        th[c][d] = h; tl[c][d] = l;
    }
    __syncthreads();
#pragma unroll 4
    for (int dd = 0; dd < 16; dd++) {
        int d = (t >> 6) * 16 + dd;
        int c = t & 63;
        size_t gi = (size_t)(bd + d) * NCODES + bc + c;
        g_CThi[gi] = th[c][d];
        g_CTlo[gi] = tl[c][d];
    }
}

// ---------------- HMMA GEMM (R5-validated) + gumbel producer CTAs -----------
// Tile 128x128, 4 warps of 64x64, BK=32.
// MODE 0: grid (64, 144). blockIdx.y < 16 -> gumbel producer CTA (writes g_G);
//         else GEMM CTA for row tile (blockIdx.y - 16), writes logits.
// MODE 1: grid (2, 128), z_q GEMM + fused z_q_st/SSE epilogue.
#define ASTR 40
#define TILE_B (128 * ASTR * 2)
#define PROD_Y 16

template<int MODE>
__global__ __launch_bounds__(128) void gemm_mma(const float* __restrict__ Z,
                                                float* __restrict__ Out) {
    if (MODE == 0 && blockIdx.y < PROD_Y) {
        // -------- gumbel producer: 1024 CTAs x 131072 elems --------
        uint32_t pid = blockIdx.y * 64 + blockIdx.x;
        uint32_t base = pid * 131072u;
        int tid = threadIdx.x;
#pragma unroll 4
        for (int i = 0; i < 256; i++) {
            uint32_t j = base + (uint32_t)(i * 128 + tid) * 4u;
            float4 v = make_float4(gumbel_at(j), gumbel_at(j + 1u),
                                   gumbel_at(j + 2u), gumbel_at(j + 3u));
            *(float4*)(g_G + j) = v;
        }
        return;
    }

    __shared__ fp16 sA[2][128 * ASTR];
    __shared__ fp16 sB[2][128 * ASTR];
    __shared__ float ssum[4];

    int tid = threadIdx.x, lane = tid & 31, wid = tid >> 5;
    int wm = wid >> 1, wn = wid & 1;
    int by = (MODE == 0) ? (blockIdx.y - PROD_Y) : blockIdx.y;
    int m0 = by * 128, n0 = blockIdx.x * 128;

    const int NIT = (MODE == 0) ? 24 : 768;
    const int sAs = (MODE == 0) ? KDIM : NCODES;

    const fp16* At[3]; const fp16* Bt[3];
    if (MODE == 0) {
        At[0] = g_Ahi; At[1] = g_Alo; At[2] = g_Ahi;
        Bt[0] = g_Bhi; Bt[1] = g_Bhi; Bt[2] = g_Blo;
    } else {
        At[0] = g_Whi; At[1] = g_Wlo; At[2] = g_Whi;
        Bt[0] = g_CThi; Bt[1] = g_CThi; Bt[2] = g_CTlo;
    }

    uint32_t sA0 = smem_u32(&sA[0][0]);
    uint32_t sB0 = smem_u32(&sB[0][0]);

    float acc[4][8][4] = {};

    auto load_stage = [&](int it, int s) {
        int term = (MODE == 0) ? (it >> 3) : (it >> 8);
        int k0   = (MODE == 0) ? ((it & 7) * 32) : ((it & 255) * 32);
        const fp16* A = At[term];
        const fp16* B = Bt[term];
        uint32_t da = sA0 + s * TILE_B;
        uint32_t db = sB0 + s * TILE_B;
#pragma unroll
        for (int i = 0; i < 4; i++) {
            int idx = tid + i * 128;
            int row = idx >> 2, ch = idx & 3;
            cp16(da + row * 80 + ch * 16, A + (size_t)(m0 + row) * sAs + k0 + ch * 8);
            cp16(db + row * 80 + ch * 16, B + (size_t)(n0 + row) * sAs + k0 + ch * 8);
        }
        cp_commit();
    };

    load_stage(0, 0);
    for (int it = 0; it < NIT; it++) {
        int s = it & 1;
        cp_wait<0>();
        __syncthreads();
        if (it + 1 < NIT) load_stage(it + 1, s ^ 1);

        uint32_t da = sA0 + s * TILE_B;
        uint32_t db = sB0 + s * TILE_B;
#pragma unroll
        for (int ks = 0; ks < 32; ks += 16) {
            uint32_t af[4][4], bq[4][4];
#pragma unroll
            for (int mt = 0; mt < 4; mt++)
                ldsm4(af[mt], da + (uint32_t)((wm * 64 + mt * 16 + (lane & 15)) * 80
                                              + (ks + ((lane >> 4) << 3)) * 2));
#pragma unroll
            for (int np = 0; np < 4; np++)
                ldsm4(bq[np], db + (uint32_t)((wn * 64 + np * 16 + (lane & 7) + ((lane >> 4) << 3)) * 80
                                              + (ks + (((lane >> 3) & 1) << 3)) * 2));
#pragma unroll
            for (int mt = 0; mt < 4; mt++)
#pragma unroll
                for (int nt = 0; nt < 8; nt++)
                    mma16816(acc[mt][nt], af[mt], &bq[nt >> 1][(nt & 1) * 2]);
        }
    }

    // ---------------- epilogue ----------------
    int rbase = m0 + wm * 64 + (lane >> 2);
    int cbase = n0 + wn * 64 + (lane & 3) * 2;
    if (MODE == 0) {
#pragma unroll
        for (int mt = 0; mt < 4; mt++)
#pragma unroll
            for (int nt = 0; nt < 8; nt++) {
                int r0 = rbase + mt * 16, c0 = cbase + nt * 8;
                *(float2*)(g_logits + (size_t)r0 * NCODES + c0)       = make_float2(acc[mt][nt][0], acc[mt][nt][1]);
                *(float2*)(g_logits + (size_t)(r0 + 8) * NCODES + c0) = make_float2(acc[mt][nt][2], acc[mt][nt][3]);
            }
    } else {
        float sse = 0.f;
#pragma unroll
        for (int mt = 0; mt < 4; mt++)
#pragma unroll
            for (int nt = 0; nt < 8; nt++) {
                int r0 = rbase + mt * 16, c0 = cbase + nt * 8;
#pragma unroll
                for (int h = 0; h < 2; h++) {
                    size_t o = (size_t)(r0 + h * 8) * KDIM + c0;
                    float2 zv = *(const float2*)(Z + o);
                    float dx = acc[mt][nt][h * 2]     - zv.x;
                    float dy = acc[mt][nt][h * 2 + 1] - zv.y;
                    sse += dx * dx + dy * dy;
                    *(float2*)(Out + o) = make_float2(zv.x + dx, zv.y + dy);
                }
            }
#pragma unroll
        for (int o = 16; o; o >>= 1) sse += __shfl_xor_sync(0xffffffffu, sse, o);
        if (lane == 0) ssum[wid] = sse;
        __syncthreads();
        if (tid == 0)
            g_sse[blockIdx.y * 2 + blockIdx.x] = ssum[0] + ssum[1] + ssum[2] + ssum[3];
    }
}

// ---------------- rowops: single pass, no threefry --------------------------
__global__ __launch_bounds__(256) void rowops(float* __restrict__ outCodes) {
    extern __shared__ float sy[];            // 8192 y values
    __shared__ float scv[8];
    __shared__ int   sci[8];

    int r = blockIdx.x;
    const float* L = g_logits + (size_t)r * NCODES;
    const float* G = g_G + (size_t)r * NCODES;

    float mx = -3.4e38f; int ai = 0;
    float se = 0.f, sel = 0.f, sys = 0.f;
    for (int c = threadIdx.x; c < NCODES; c += 256) {
        float l = L[c];
        float y = l + G[c];
        sy[c] = y;
        float e = __expf(l - B1);
        se += e; sel += e * l;
        sys += __expf(y - B2);
        if (l > mx) { mx = l; ai = c; }
    }
    __syncthreads();

    blockArgmax(mx, ai, scv, sci);
    float SE  = blockSum(se, scv);
    float SEl = blockSum(sel, scv);
    float SY  = blockSum(sys, scv);

    float inv = 1.0f / SY;
    fp16* wh = g_Whi + (size_t)r * NCODES;
    fp16* wl = g_Wlo + (size_t)r * NCODES;
    for (int c = threadIdx.x; c < NCODES; c += 256) {
        float w = __expf(sy[c] - B2) * inv;
        fp16 h = __float2half_rn(w);
        wh[c] = h;
        wl[c] = __float2half_rn(w - __half2float(h));
    }
    if (threadIdx.x == 0) {
        g_kl[r] = SEl / SE - (B1 + __logf(SE)) + 9.0109131f;   // + ln 8192
        outCodes[r] = (float)ai;
    }
}

// ---------------- finalize --------------------------------------------------
__global__ __launch_bounds__(256) void finalize(float* __restrict__ outLoss) {
    __shared__ float sc[8];
    float k = 0.f;
    for (int i = threadIdx.x; i < NROWS; i += 256) k += g_kl[i];
    float K = blockSum(k, sc);
    float E = blockSum(g_sse[threadIdx.x], sc);
    if (threadIdx.x == 0)
        outLoss[0] = 0.25f * (E / (float)ZELEMS) + 0.01f * (K / (float)NROWS);
}

// ---------------- launch ----------------------------------------------------
extern "C" void kernel_launch(void* const* d_in, const int* in_sizes, int n_in,
                              void* d_out, int out_size) {
    const float* z  = (const float*)d_in[0];
    const float* cb = (const float*)d_in[1];
    float* out = (float*)d_out;
    float* outZ     = out;
    float* outLoss  = out + ZELEMS;
    float* outCodes = out + ZELEMS + 1;

    split_z<<<ZELEMS / 256, 256>>>(z);
    dim3 gs(NCODES / 64, KDIM / 64);
    split_cb<<<gs, 256>>>(cb);

    dim3 g1(NCODES / 128, NROWS / 128 + PROD_Y);   // (64, 144): 1024 producers + 8192 gemm
    gemm_mma<0><<<g1, 128>>>(nullptr, nullptr);

    rowops<<<NROWS, 256, NCODES * 4>>>(outCodes);

    dim3 g2(KDIM / 128, NROWS / 128);              // (2, 128)
    gemm_mma<1><<<g2, 128>>>(z, outZ);

    finalize<<<1, 256>>>(outLoss);
}